// round 2
// baseline (speedup 1.0000x reference)
#include <cuda_runtime.h>
#include <cuda_bf16.h>

// VolumeSDFRenderer: R=65536 rays, N=128 samples.
// inputs (metadata order): distance [R,N] f32, color [R,N,3] f32, depth_values [R,N] f32
// output: concat(out_color [R,3], geometry zeros [R,N,3]) as f32.
//
// One warp per ray. Lane k owns samples [4k, 4k+4). Coalesced float4 loads,
// warp-shuffle exclusive scan for the transmittance cumsum (shift-by-one of the
// inclusive scan — NOT incl - lane_sum, which catastrophically cancels against
// the FAR_DELTA term in lane 31), shfl_xor reduce for the weighted color sum.
// Geometry region zeroed by cudaMemsetAsync.

#define ALPHA 10.0f
#define INV_BETA 20.0f      // 1/0.05
#define FAR_DELTA 1e10f

__device__ __forceinline__ float sdf_density(float dist) {
    float s = -dist;
    float e = __expf(-INV_BETA * fabsf(s));
    // s<=0: alpha*0.5*exp(s/beta) = 5*e ; s>0: alpha*(1-0.5*exp(-s/beta)) = 10 - 5*e
    return (s <= 0.0f) ? (0.5f * ALPHA * e) : (ALPHA - 0.5f * ALPHA * e);
}

__global__ __launch_bounds__(256, 8)
void volume_sdf_kernel(const float* __restrict__ distance,
                       const float* __restrict__ color,
                       const float* __restrict__ depth,
                       float* __restrict__ out_color,
                       int n_rays)
{
    const int warp_id = (blockIdx.x * blockDim.x + threadIdx.x) >> 5;
    const int lane    = threadIdx.x & 31;
    if (warp_id >= n_rays) return;
    const int ray = warp_id;

    const size_t base128 = (size_t)ray * 128;

    // ---- loads: 4 samples per lane, fully coalesced ----
    const float4 d4 = reinterpret_cast<const float4*>(distance + base128)[lane];
    const float4 t4 = reinterpret_cast<const float4*>(depth    + base128)[lane];

    // color: 12 floats per lane = 3 x float4 (48B-aligned offsets)
    const float4* cp = reinterpret_cast<const float4*>(color + (size_t)ray * 384) + lane * 3;
    const float4 ca = cp[0];
    const float4 cb = cp[1];
    const float4 cc = cp[2];

    // ---- deltas: need t[4k+4] = next lane's t4.x ----
    float t_next = __shfl_down_sync(0xffffffffu, t4.x, 1);
    float dlt0 = t4.y - t4.x;
    float dlt1 = t4.z - t4.y;
    float dlt2 = t4.w - t4.z;
    float dlt3 = (lane == 31) ? FAR_DELTA : (t_next - t4.w);

    // ---- d = density * delta ----
    float dd0 = sdf_density(d4.x) * dlt0;
    float dd1 = sdf_density(d4.y) * dlt1;
    float dd2 = sdf_density(d4.z) * dlt2;
    float dd3 = sdf_density(d4.w) * dlt3;

    // ---- local exclusive prefix within lane ----
    float e0 = 0.0f;
    float e1 = dd0;
    float e2 = e1 + dd1;
    float e3 = e2 + dd2;
    float lane_sum = e3 + dd3;

    // ---- warp inclusive scan of lane sums ----
    float x = lane_sum;
    #pragma unroll
    for (int off = 1; off < 32; off <<= 1) {
        float y = __shfl_up_sync(0xffffffffu, x, off);
        if (lane >= off) x += y;
    }
    // exclusive prefix = previous lane's inclusive value (exact; avoids
    // subtracting lane 31's huge FAR_DELTA-contaminated lane_sum)
    float excl = __shfl_up_sync(0xffffffffu, x, 1);
    if (lane == 0) excl = 0.0f;

    // ---- weights & weighted color accumulation ----
    float w0 = (1.0f - __expf(-dd0)) * __expf(-(excl + e0));
    float w1 = (1.0f - __expf(-dd1)) * __expf(-(excl + e1));
    float w2 = (1.0f - __expf(-dd2)) * __expf(-(excl + e2));
    float w3 = (1.0f - __expf(-dd3)) * __expf(-(excl + e3));

    // unpack 12 floats -> 4 rgb samples
    float r = w0 * ca.x + w1 * ca.w + w2 * cb.z + w3 * cc.y;
    float g = w0 * ca.y + w1 * cb.x + w2 * cb.w + w3 * cc.z;
    float b = w0 * ca.z + w1 * cb.y + w2 * cc.x + w3 * cc.w;

    // ---- warp reduction ----
    #pragma unroll
    for (int off = 16; off >= 1; off >>= 1) {
        r += __shfl_xor_sync(0xffffffffu, r, off);
        g += __shfl_xor_sync(0xffffffffu, g, off);
        b += __shfl_xor_sync(0xffffffffu, b, off);
    }

    if (lane == 0) {
        out_color[(size_t)ray * 3 + 0] = r;
        out_color[(size_t)ray * 3 + 1] = g;
        out_color[(size_t)ray * 3 + 2] = b;
    }
}

extern "C" void kernel_launch(void* const* d_in, const int* in_sizes, int n_in,
                              void* d_out, int out_size)
{
    const float* distance = (const float*)d_in[0];
    const float* color    = (const float*)d_in[1];
    const float* depth    = (const float*)d_in[2];
    float* out = (float*)d_out;

    const int n_rays = in_sizes[0] / 128;   // R = 65536

    // zero the whole output: geometry region must be 0; out_color overwritten below
    cudaMemsetAsync(d_out, 0, (size_t)out_size * sizeof(float));

    // one warp per ray; 256 threads = 8 warps per block
    const int warps_per_block = 8;
    const int blocks = (n_rays + warps_per_block - 1) / warps_per_block;
    volume_sdf_kernel<<<blocks, 256>>>(distance, color, depth, out, n_rays);
}

// round 5
// speedup vs baseline: 1.1941x; 1.1941x over previous
#include <cuda_runtime.h>
#include <cuda_bf16.h>

// VolumeSDFRenderer: R=65536 rays, N=128 samples.
// inputs (metadata order): distance [R,N] f32, color [R,N,3] f32, depth_values [R,N] f32
// output: concat(out_color [R,3], geometry zeros [R,N,3]) as f32.
//
// Single fused kernel, one warp per ray. Lane k owns samples [4k, 4k+4).
// Coalesced float4 loads; warp-shuffle exclusive scan (shift of inclusive —
// avoids FAR_DELTA cancellation in lane 31); shfl_xor color reduction.
// Geometry zeros are written by the same warp (3 coalesced float4 stores per
// lane), overlapping the write stream with the read-bound mainloop instead of
// serializing a separate 100MB memset.

#define ALPHA 10.0f
#define INV_BETA 20.0f      // 1/0.05
#define FAR_DELTA 1e10f

__device__ __forceinline__ float sdf_density(float dist) {
    float s = -dist;
    float e = __expf(-INV_BETA * fabsf(s));
    // s<=0: alpha*0.5*exp(s/beta) = 5*e ; s>0: alpha*(1-0.5*exp(-s/beta)) = 10 - 5*e
    return (s <= 0.0f) ? (0.5f * ALPHA * e) : (ALPHA - 0.5f * ALPHA * e);
}

__global__ __launch_bounds__(256, 8)
void volume_sdf_fused_kernel(const float* __restrict__ distance,
                             const float* __restrict__ color,
                             const float* __restrict__ depth,
                             float* __restrict__ out,          // full output buffer
                             int n_rays)
{
    const int warp_id = (blockIdx.x * blockDim.x + threadIdx.x) >> 5;
    const int lane    = threadIdx.x & 31;
    if (warp_id >= n_rays) return;
    const int ray = warp_id;

    const size_t base128 = (size_t)ray * 128;

    // ---- loads: 4 samples per lane, fully coalesced ----
    const float4 d4 = reinterpret_cast<const float4*>(distance + base128)[lane];
    const float4 t4 = reinterpret_cast<const float4*>(depth    + base128)[lane];

    // ---- zero this ray's geometry slab: 384 floats = 96 float4, coalesced ----
    // issued early so the stores drain while the math below runs
    {
        float4* geo = reinterpret_cast<float4*>(out + (size_t)n_rays * 3 + (size_t)ray * 384);
        const float4 z = make_float4(0.f, 0.f, 0.f, 0.f);
        geo[lane]      = z;
        geo[lane + 32] = z;
        geo[lane + 64] = z;
    }

    // color: 12 floats per lane = 3 x float4 (48B-aligned offsets)
    const float4* cp = reinterpret_cast<const float4*>(color + (size_t)ray * 384) + lane * 3;
    const float4 ca = cp[0];
    const float4 cb = cp[1];
    const float4 cc = cp[2];

    // ---- deltas: need t[4k+4] = next lane's t4.x ----
    float t_next = __shfl_down_sync(0xffffffffu, t4.x, 1);
    float dlt0 = t4.y - t4.x;
    float dlt1 = t4.z - t4.y;
    float dlt2 = t4.w - t4.z;
    float dlt3 = (lane == 31) ? FAR_DELTA : (t_next - t4.w);

    // ---- d = density * delta ----
    float dd0 = sdf_density(d4.x) * dlt0;
    float dd1 = sdf_density(d4.y) * dlt1;
    float dd2 = sdf_density(d4.z) * dlt2;
    float dd3 = sdf_density(d4.w) * dlt3;

    // ---- local exclusive prefix within lane ----
    float e1 = dd0;
    float e2 = e1 + dd1;
    float e3 = e2 + dd2;
    float lane_sum = e3 + dd3;

    // ---- warp inclusive scan of lane sums ----
    float x = lane_sum;
    #pragma unroll
    for (int off = 1; off < 32; off <<= 1) {
        float y = __shfl_up_sync(0xffffffffu, x, off);
        if (lane >= off) x += y;
    }
    // exclusive prefix = previous lane's inclusive value (exact; avoids
    // subtracting lane 31's huge FAR_DELTA-contaminated lane_sum)
    float excl = __shfl_up_sync(0xffffffffu, x, 1);
    if (lane == 0) excl = 0.0f;

    // ---- weights & weighted color accumulation ----
    float w0 = (1.0f - __expf(-dd0)) * __expf(-excl);
    float w1 = (1.0f - __expf(-dd1)) * __expf(-(excl + e1));
    float w2 = (1.0f - __expf(-dd2)) * __expf(-(excl + e2));
    float w3 = (1.0f - __expf(-dd3)) * __expf(-(excl + e3));

    // unpack 12 floats -> 4 rgb samples
    float r = w0 * ca.x + w1 * ca.w + w2 * cb.z + w3 * cc.y;
    float g = w0 * ca.y + w1 * cb.x + w2 * cb.w + w3 * cc.z;
    float b = w0 * ca.z + w1 * cb.y + w2 * cc.x + w3 * cc.w;

    // ---- warp reduction ----
    #pragma unroll
    for (int off = 16; off >= 1; off >>= 1) {
        r += __shfl_xor_sync(0xffffffffu, r, off);
        g += __shfl_xor_sync(0xffffffffu, g, off);
        b += __shfl_xor_sync(0xffffffffu, b, off);
    }

    if (lane == 0) {
        out[(size_t)ray * 3 + 0] = r;
        out[(size_t)ray * 3 + 1] = g;
        out[(size_t)ray * 3 + 2] = b;
    }
}

extern "C" void kernel_launch(void* const* d_in, const int* in_sizes, int n_in,
                              void* d_out, int out_size)
{
    const float* distance = (const float*)d_in[0];
    const float* color    = (const float*)d_in[1];
    const float* depth    = (const float*)d_in[2];
    float* out = (float*)d_out;

    const int n_rays = in_sizes[0] / 128;   // R = 65536

    // one warp per ray; 256 threads = 8 warps per block
    const int warps_per_block = 8;
    const int blocks = (n_rays + warps_per_block - 1) / warps_per_block;
    volume_sdf_fused_kernel<<<blocks, 256>>>(distance, color, depth, out, n_rays);
}

// round 6
// speedup vs baseline: 1.1950x; 1.0007x over previous
#include <cuda_runtime.h>
#include <cuda_bf16.h>

// VolumeSDFRenderer: R=65536 rays, N=128 samples.
// inputs (metadata order): distance [R,N] f32, color [R,N,3] f32, depth_values [R,N] f32
// output: concat(out_color [R,3], geometry zeros [R,N,3]) as f32.
//
// Single fused kernel, one warp per ray. Lane k owns samples [4k, 4k+4).
// All five input float4 loads are front-batched (MLP=5) with streaming hints
// (__ldcs: no reuse, evict-first), geometry zeros written with __stcs so the
// 100MB zero stream doesn't thrash L2 against the 167MB read stream.
// Warp-shuffle exclusive scan (shift of inclusive — avoids FAR_DELTA
// cancellation in lane 31); shfl_xor color reduction.

#define ALPHA 10.0f
#define INV_BETA 20.0f      // 1/0.05
#define FAR_DELTA 1e10f

__device__ __forceinline__ float sdf_density(float dist) {
    float s = -dist;
    float e = __expf(-INV_BETA * fabsf(s));
    // s<=0: alpha*0.5*exp(s/beta) = 5*e ; s>0: alpha*(1-0.5*exp(-s/beta)) = 10 - 5*e
    return (s <= 0.0f) ? (0.5f * ALPHA * e) : (ALPHA - 0.5f * ALPHA * e);
}

__global__ __launch_bounds__(256, 8)
void volume_sdf_fused_kernel(const float* __restrict__ distance,
                             const float* __restrict__ color,
                             const float* __restrict__ depth,
                             float* __restrict__ out,          // full output buffer
                             int n_rays)
{
    const int warp_id = (blockIdx.x * blockDim.x + threadIdx.x) >> 5;
    const int lane    = threadIdx.x & 31;
    if (warp_id >= n_rays) return;
    const int ray = warp_id;

    const size_t base128 = (size_t)ray * 128;

    // ---- front-batched loads: 5 independent float4 LDGs, streaming policy ----
    const float4 d4 = __ldcs(reinterpret_cast<const float4*>(distance + base128) + lane);
    const float4 t4 = __ldcs(reinterpret_cast<const float4*>(depth    + base128) + lane);
    const float4* cp = reinterpret_cast<const float4*>(color + (size_t)ray * 384) + lane * 3;
    const float4 ca = __ldcs(cp + 0);
    const float4 cb = __ldcs(cp + 1);
    const float4 cc = __ldcs(cp + 2);

    // ---- zero this ray's geometry slab: 384 floats = 96 float4, coalesced ----
    // streaming stores: drain to DRAM without occupying L2 ways
    {
        float4* geo = reinterpret_cast<float4*>(out + (size_t)n_rays * 3 + (size_t)ray * 384);
        const float4 z = make_float4(0.f, 0.f, 0.f, 0.f);
        __stcs(geo + lane,      z);
        __stcs(geo + lane + 32, z);
        __stcs(geo + lane + 64, z);
    }

    // ---- deltas: need t[4k+4] = next lane's t4.x ----
    float t_next = __shfl_down_sync(0xffffffffu, t4.x, 1);
    float dlt0 = t4.y - t4.x;
    float dlt1 = t4.z - t4.y;
    float dlt2 = t4.w - t4.z;
    float dlt3 = (lane == 31) ? FAR_DELTA : (t_next - t4.w);

    // ---- d = density * delta ----
    float dd0 = sdf_density(d4.x) * dlt0;
    float dd1 = sdf_density(d4.y) * dlt1;
    float dd2 = sdf_density(d4.z) * dlt2;
    float dd3 = sdf_density(d4.w) * dlt3;

    // ---- local exclusive prefix within lane ----
    float e1 = dd0;
    float e2 = e1 + dd1;
    float e3 = e2 + dd2;
    float lane_sum = e3 + dd3;

    // ---- warp inclusive scan of lane sums ----
    float x = lane_sum;
    #pragma unroll
    for (int off = 1; off < 32; off <<= 1) {
        float y = __shfl_up_sync(0xffffffffu, x, off);
        if (lane >= off) x += y;
    }
    // exclusive prefix = previous lane's inclusive value (exact; avoids
    // subtracting lane 31's huge FAR_DELTA-contaminated lane_sum)
    float excl = __shfl_up_sync(0xffffffffu, x, 1);
    if (lane == 0) excl = 0.0f;

    // ---- weights & weighted color accumulation ----
    float w0 = (1.0f - __expf(-dd0)) * __expf(-excl);
    float w1 = (1.0f - __expf(-dd1)) * __expf(-(excl + e1));
    float w2 = (1.0f - __expf(-dd2)) * __expf(-(excl + e2));
    float w3 = (1.0f - __expf(-dd3)) * __expf(-(excl + e3));

    // unpack 12 floats -> 4 rgb samples
    float r = w0 * ca.x + w1 * ca.w + w2 * cb.z + w3 * cc.y;
    float g = w0 * ca.y + w1 * cb.x + w2 * cb.w + w3 * cc.z;
    float b = w0 * ca.z + w1 * cb.y + w2 * cc.x + w3 * cc.w;

    // ---- warp reduction ----
    #pragma unroll
    for (int off = 16; off >= 1; off >>= 1) {
        r += __shfl_xor_sync(0xffffffffu, r, off);
        g += __shfl_xor_sync(0xffffffffu, g, off);
        b += __shfl_xor_sync(0xffffffffu, b, off);
    }

    if (lane == 0) {
        out[(size_t)ray * 3 + 0] = r;
        out[(size_t)ray * 3 + 1] = g;
        out[(size_t)ray * 3 + 2] = b;
    }
}

extern "C" void kernel_launch(void* const* d_in, const int* in_sizes, int n_in,
                              void* d_out, int out_size)
{
    const float* distance = (const float*)d_in[0];
    const float* color    = (const float*)d_in[1];
    const float* depth    = (const float*)d_in[2];
    float* out = (float*)d_out;

    const int n_rays = in_sizes[0] / 128;   // R = 65536

    // one warp per ray; 256 threads = 8 warps per block
    const int warps_per_block = 8;
    const int blocks = (n_rays + warps_per_block - 1) / warps_per_block;
    volume_sdf_fused_kernel<<<blocks, 256>>>(distance, color, depth, out, n_rays);
}